// round 1
// baseline (speedup 1.0000x reference)
#include <cuda_runtime.h>

typedef unsigned long long ull;

#define NPART   262144
#define WD      128
#define TM      128
#define NTH     256
#define NTILES  (NPART / TM)   // 2048
#define TSTEPS  101
#define W0F     44.0f

// Persistent ODE state (device globals: no allocation allowed)
__device__ float g_y [NPART * 2];
__device__ float g_k1[NPART * 2];
__device__ float g_k2[NPART * 2];
__device__ float g_k3[NPART * 2];
// W2 pre-duplicated into f32x2 pairs, permuted for conflict-free LDS:
// slot [k*128 + c*16 + tx] holds dup(W2[k][tx*8 + c])
__device__ ull g_W2d[WD * WD];

// ---------------------------------------------------------------------------
// sin with explicit Cody-Waite 2*pi reduction, then MUFU.SIN (__sinf).
// Layer-1 args reach |x| ~ 130; after reduction |r| <= pi where __sinf's
// abs error is ~2^-21.4. n*C1 is exact (C1 has 9 mantissa bits, |n| < 32).
// ---------------------------------------------------------------------------
__device__ __forceinline__ float fast_sin(float x) {
    float n = rintf(x * 0.15915494f);          // 1/(2*pi)
    float r = fmaf(n, -6.28125f, x);           // 2*pi hi
    r = fmaf(n, -1.9353072e-3f, r);            // 2*pi lo
    return __sinf(r);
}

__device__ __forceinline__ ull fma2(ull a, ull b, ull c) {
    ull d;
    asm("fma.rn.f32x2 %0, %1, %2, %3;" : "=l"(d) : "l"(a), "l"(b), "l"(c));
    return d;
}

__device__ __forceinline__ void unpack2(ull v, float& lo, float& hi) {
    asm("mov.b64 {%0, %1}, %2;" : "=f"(lo), "=f"(hi) : "l"(v));
}

// ---------------------------------------------------------------------------
// Pre-duplicate + permute W2 once per launch call.
// ---------------------------------------------------------------------------
__global__ void dup_w2_kernel(const float* __restrict__ W2) {
    int i = blockIdx.x * blockDim.x + threadIdx.x;
    if (i < WD * WD) {
        int k = i >> 7;
        int j = i & 127;
        float v = W2[i];
        ull r;
        asm("mov.b64 %0, {%1, %1};" : "=l"(r) : "f"(v));
        g_W2d[(k << 7) + ((j & 7) << 4) + (j >> 3)] = r;
    }
}

// ---------------------------------------------------------------------------
// One fused f-evaluation over all particles (persistent grid-stride kernel).
//   x = y + dt*(c1*k1 + c2*k2 + c3*k3)         (mode selects how many k's)
//   h1 = sin(w0*(x@W1 + b1))                    -> SMEM, transposed [k][m]
//   pre = h1 @ W2                               -> f32x2 register tile GEMM
//   h2 = sin(w0*(pre + b2));  f = h2@W3 + b3    -> cross-thread reduction
//   mode<3 : write f into k{1,2,3}
//   mode==3: k4=f; y += (k1+3(k2+k3)+k4)*dt/8; write y and out[step+1]
// ---------------------------------------------------------------------------
__global__ void __launch_bounds__(NTH, 1) ode_eval_kernel(
    const float* __restrict__ t,
    const float* __restrict__ W1, const float* __restrict__ b1,
    const float* __restrict__ b2,
    const float* __restrict__ W3, const float* __restrict__ b3,
    float* __restrict__ out,
    int step, int mode, float c1, float c2, float c3)
{
    extern __shared__ float smem[];
    ull*   sW2d = (ull*)smem;                  // 16384 ull = 131072 B
    float* hT   = smem + 2 * WD * WD;          // 16384 f   =  65536 B
    float* sx   = hT + WD * TM;                // 256 f
    float* sW1a = sx + 2 * TM;                 // 128
    float* sW1b = sW1a + WD;                   // 128
    float* sb1  = sW1b + WD;                   // 128
    float* sb2  = sb1 + WD;                    // 128
    float* sW3x = sb2 + WD;                    // 128
    float* sW3y = sW3x + WD;                   // 128

    const int tid = threadIdx.x;
    const float dt = t[step + 1] - t[step];

    // Load W2 (duplicated) + small params into SMEM once per CTA.
    {
        const float4* src = (const float4*)g_W2d;
        float4* dst = (float4*)sW2d;
        for (int i = tid; i < (2 * WD * WD) / 4; i += NTH) dst[i] = src[i];
        if (tid < WD) {
            sW1a[tid] = W1[tid];
            sW1b[tid] = W1[WD + tid];
            sb1[tid]  = b1[tid];
            sb2[tid]  = b2[tid];
            sW3x[tid] = W3[2 * tid];
            sW3y[tid] = W3[2 * tid + 1];
        }
    }
    __syncthreads();

    const int txv  = tid & 15;
    const int mrow = (tid >> 4) << 3;  // 8 particles per thread (4 f32x2 pairs)
    const int jcol = txv << 3;         // 8 hidden columns per thread

    for (int tile = blockIdx.x; tile < NTILES; tile += gridDim.x) {
        const int base = tile * TM;

        // ---- Phase A1: combined input state x for this tile ----
        if (tid < TM) {
            int gm = base + tid;
            float yv0 = g_y[2 * gm], yv1 = g_y[2 * gm + 1];
            float a0 = 0.f, a1 = 0.f;
            if (mode >= 1) { a0 = c1 * g_k1[2 * gm];        a1 = c1 * g_k1[2 * gm + 1]; }
            if (mode >= 2) { a0 = fmaf(c2, g_k2[2 * gm], a0); a1 = fmaf(c2, g_k2[2 * gm + 1], a1); }
            if (mode >= 3) { a0 = fmaf(c3, g_k3[2 * gm], a0); a1 = fmaf(c3, g_k3[2 * gm + 1], a1); }
            sx[2 * tid]     = fmaf(dt, a0, yv0);
            sx[2 * tid + 1] = fmaf(dt, a1, yv1);
        }
        __syncthreads();

        // ---- Phase A2: h1 = sin(w0*(x@W1 + b1)), stored transposed [j][m] ----
        for (int i = tid; i < TM * WD; i += NTH) {
            int m = i & (TM - 1);
            int j = i >> 7;
            float arg = W0F * (sx[2 * m] * sW1a[j] + sx[2 * m + 1] * sW1b[j] + sb1[j]);
            hT[j * TM + m] = fast_sin(arg);
        }
        __syncthreads();

        // ---- Phase B: 128x128x128 GEMM tile with f32x2 packed FMAs ----
        ull acc[4][8];
        #pragma unroll
        for (int p = 0; p < 4; p++)
            #pragma unroll
            for (int c = 0; c < 8; c++) acc[p][c] = 0ULL;

        #pragma unroll 4
        for (int k = 0; k < WD; k++) {
            const ull* arow = (const ull*)(hT + k * TM + mrow);
            ull a[4];
            #pragma unroll
            for (int p = 0; p < 4; p++) a[p] = arow[p];
            const ull* wrow = sW2d + (k << 7) + txv;
            ull w[8];
            #pragma unroll
            for (int c = 0; c < 8; c++) w[c] = wrow[c << 4];
            #pragma unroll
            for (int p = 0; p < 4; p++)
                #pragma unroll
                for (int c = 0; c < 8; c++)
                    acc[p][c] = fma2(a[p], w[c], acc[p][c]);
        }

        // ---- Phase C: h2 = sin(w0*(acc+b2)); partial f = h2 @ W3 ----
        float o0[8], o1[8];
        #pragma unroll
        for (int i = 0; i < 8; i++) { o0[i] = 0.f; o1[i] = 0.f; }
        #pragma unroll
        for (int c = 0; c < 8; c++) {
            int j = jcol + c;
            float bb = sb2[j], wx = sW3x[j], wy = sW3y[j];
            #pragma unroll
            for (int p = 0; p < 4; p++) {
                float lo, hi;
                unpack2(acc[p][c], lo, hi);
                float hlo = fast_sin(W0F * (lo + bb));
                float hhi = fast_sin(W0F * (hi + bb));
                o0[2 * p]     = fmaf(hlo, wx, o0[2 * p]);
                o1[2 * p]     = fmaf(hlo, wy, o1[2 * p]);
                o0[2 * p + 1] = fmaf(hhi, wx, o0[2 * p + 1]);
                o1[2 * p + 1] = fmaf(hhi, wy, o1[2 * p + 1]);
            }
        }
        __syncthreads();  // all threads done reading hT; reuse it as scratch

        // red[u][m*2+c], row stride 258 floats (bank-skewed)
        float* red = hT;
        #pragma unroll
        for (int i = 0; i < 8; i++) {
            int m = mrow + i;
            red[txv * 258 + m * 2 + 0] = o0[i];
            red[txv * 258 + m * 2 + 1] = o1[i];
        }
        __syncthreads();

        // ---- Phase D: reduce 16 partials per (particle, dim); emit ----
        {
            const float* r = red + tid;   // tid = m*2 + c
            float s = 0.f;
            #pragma unroll
            for (int u = 0; u < 16; u++) s += r[u * 258];
            s += b3[tid & 1];
            int gi = 2 * base + tid;
            if (mode < 3) {
                float* kdst = (mode == 0) ? g_k1 : (mode == 1) ? g_k2 : g_k3;
                kdst[gi] = s;
            } else {
                float K1 = g_k1[gi], K2 = g_k2[gi], K3 = g_k3[gi];
                float y1 = g_y[gi] + (K1 + 3.0f * (K2 + K3) + s) * (dt * 0.125f);
                g_y[gi] = y1;
                out[(size_t)(step + 1) * (NPART * 2) + gi] = y1;
            }
        }
        __syncthreads();  // before next tile reuses sx / hT
    }
}

// ---------------------------------------------------------------------------
// Host launcher: graph-capturable, allocation-free.
// Inputs (metadata order): t, x0, W1, b1, W2, b2, W3, b3. Output float32.
// ---------------------------------------------------------------------------
extern "C" void kernel_launch(void* const* d_in, const int* in_sizes, int n_in,
                              void* d_out, int out_size) {
    const float* t  = (const float*)d_in[0];
    const float* x0 = (const float*)d_in[1];
    const float* W1 = (const float*)d_in[2];
    const float* b1 = (const float*)d_in[3];
    const float* W2 = (const float*)d_in[4];
    const float* b2 = (const float*)d_in[5];
    const float* W3 = (const float*)d_in[6];
    const float* b3 = (const float*)d_in[7];
    float* out = (float*)d_out;

    const size_t state_bytes = (size_t)NPART * 2 * sizeof(float);

    // out[0] = x0 ; y = x0  (re-initialize every call: deterministic replay)
    cudaMemcpyAsync(out, x0, state_bytes, cudaMemcpyDeviceToDevice);
    cudaMemcpyToSymbolAsync(g_y, x0, state_bytes, 0, cudaMemcpyDeviceToDevice);

    dup_w2_kernel<<<(WD * WD + 255) / 256, 256>>>(W2);

    const int smem_bytes = (2 * WD * WD + WD * TM + 2 * TM + 6 * WD) * (int)sizeof(float); // 200704
    cudaFuncSetAttribute(ode_eval_kernel,
                         cudaFuncAttributeMaxDynamicSharedMemorySize, smem_bytes);

    int nsm = 148;
    cudaDeviceGetAttribute(&nsm, cudaDevAttrMultiProcessorCount, 0);

    for (int s = 0; s < TSTEPS - 1; s++) {
        // k1 = f(y)
        ode_eval_kernel<<<nsm, NTH, smem_bytes>>>(t, W1, b1, b2, W3, b3, out,
                                                  s, 0, 0.f, 0.f, 0.f);
        // k2 = f(y + dt*k1/3)
        ode_eval_kernel<<<nsm, NTH, smem_bytes>>>(t, W1, b1, b2, W3, b3, out,
                                                  s, 1, 1.0f / 3.0f, 0.f, 0.f);
        // k3 = f(y + dt*(k2 - k1/3))
        ode_eval_kernel<<<nsm, NTH, smem_bytes>>>(t, W1, b1, b2, W3, b3, out,
                                                  s, 2, -1.0f / 3.0f, 1.f, 0.f);
        // k4 = f(y + dt*(k1 - k2 + k3)); y += (k1+3(k2+k3)+k4)*dt/8
        ode_eval_kernel<<<nsm, NTH, smem_bytes>>>(t, W1, b1, b2, W3, b3, out,
                                                  s, 3, 1.f, -1.f, 1.f);
    }
}

// round 2
// speedup vs baseline: 1.3269x; 1.3269x over previous
#include <cuda_runtime.h>

typedef unsigned long long ull;

#define NPART   262144
#define WD      128
#define TM      128
#define KH      64            // k-half for hT double-use
#define NTH     256
#define NTILES  (NPART / TM)  // 2048
#define TSTEPS  101
#define W0F     44.0f

// Persistent ODE state (device globals: no allocation allowed)
__device__ float g_y [NPART * 2];
__device__ float g_k1[NPART * 2];
__device__ float g_k2[NPART * 2];
__device__ float g_k3[NPART * 2];

// ---------------------------------------------------------------------------
// sin with explicit Cody-Waite 2*pi reduction, then MUFU.SIN (__sinf).
// ---------------------------------------------------------------------------
__device__ __forceinline__ float fast_sin(float x) {
    float n = rintf(x * 0.15915494f);          // 1/(2*pi)
    float r = fmaf(n, -6.28125f, x);           // 2*pi hi
    r = fmaf(n, -1.9353072e-3f, r);            // 2*pi lo
    return __sinf(r);
}

__device__ __forceinline__ ull fma2(ull a, ull b, ull c) {
    ull d;
    asm("fma.rn.f32x2 %0, %1, %2, %3;" : "=l"(d) : "l"(a), "l"(b), "l"(c));
    return d;
}

__device__ __forceinline__ ull dup2(float v) {
    ull r;
    asm("mov.b64 %0, {%1, %1};" : "=l"(r) : "f"(v));
    return r;
}

__device__ __forceinline__ void unpack2(ull v, float& lo, float& hi) {
    asm("mov.b64 {%0, %1}, %2;" : "=f"(lo), "=f"(hi) : "l"(v));
}

// ---------------------------------------------------------------------------
// Fused f-evaluation. 2 CTAs per SM (smem ~100KB, regs capped at 128).
//   x = y + dt*(c1*k1 + c2*k2 + c3*k3)
//   h1 = sin(w0*(x@W1 + b1))     -> SMEM transposed [j][m], in 2 k-halves
//   pre = h1 @ W2                -> f32x2 register-tile GEMM (W2 plain floats
//                                   in SMEM, duplicated on the fly via MOV)
//   h2 = sin(w0*(pre + b2)); f = h2@W3 + b3 -> cross-thread reduction
// ---------------------------------------------------------------------------
__global__ void __launch_bounds__(NTH, 2) ode_eval_kernel(
    const float* __restrict__ t,
    const float* __restrict__ W1, const float* __restrict__ b1,
    const float* __restrict__ W2, const float* __restrict__ b2,
    const float* __restrict__ W3, const float* __restrict__ b3,
    float* __restrict__ out,
    int step, int mode, float c1, float c2, float c3)
{
    extern __shared__ float smem[];
    float* sW2  = smem;               // 16384 f = 64KB, permuted [k][c*16+txv]
    float* hT   = smem + WD * WD;     // KH*TM = 8192 f = 32KB
    float* sx   = hT + KH * TM;       // 256 f
    float* sW1a = sx + 2 * TM;        // 128
    float* sW1b = sW1a + WD;          // 128
    float* sb1  = sW1b + WD;          // 128
    float* sb2  = sb1 + WD;           // 128
    float* sW3x = sb2 + WD;           // 128
    float* sW3y = sW3x + WD;          // 128

    const int tid = threadIdx.x;
    const float dt = t[step + 1] - t[step];

    // Load W2 permuted (+ small params) into SMEM once per CTA.
    for (int i = tid; i < WD * WD; i += NTH) {
        int k = i >> 7;
        int j = i & 127;
        sW2[(k << 7) + ((j & 7) << 4) + (j >> 3)] = W2[i];
    }
    if (tid < WD) {
        sW1a[tid] = W1[tid];
        sW1b[tid] = W1[WD + tid];
        sb1[tid]  = b1[tid];
        sb2[tid]  = b2[tid];
        sW3x[tid] = W3[2 * tid];
        sW3y[tid] = W3[2 * tid + 1];
    }
    __syncthreads();

    const int txv  = tid & 15;
    const int mrow = (tid >> 4) << 3;  // 8 particles per thread (4 f32x2 pairs)
    const int jcol = txv << 3;         // 8 hidden columns per thread

    for (int tile = blockIdx.x; tile < NTILES; tile += gridDim.x) {
        const int base = tile * TM;

        // ---- Phase A1: combined input state x for this tile ----
        if (tid < TM) {
            int gm = base + tid;
            float yv0 = g_y[2 * gm], yv1 = g_y[2 * gm + 1];
            float a0 = 0.f, a1 = 0.f;
            if (mode >= 1) { a0 = c1 * g_k1[2 * gm];          a1 = c1 * g_k1[2 * gm + 1]; }
            if (mode >= 2) { a0 = fmaf(c2, g_k2[2 * gm], a0); a1 = fmaf(c2, g_k2[2 * gm + 1], a1); }
            if (mode >= 3) { a0 = fmaf(c3, g_k3[2 * gm], a0); a1 = fmaf(c3, g_k3[2 * gm + 1], a1); }
            sx[2 * tid]     = fmaf(dt, a0, yv0);
            sx[2 * tid + 1] = fmaf(dt, a1, yv1);
        }
        __syncthreads();

        ull acc[4][8];
        #pragma unroll
        for (int p = 0; p < 4; p++)
            #pragma unroll
            for (int c = 0; c < 8; c++) acc[p][c] = 0ULL;

        // ---- Two k-halves: build hT (64 rows) then GEMM over it ----
        #pragma unroll 1
        for (int half = 0; half < 2; half++) {
            const int j0 = half * KH;

            // Phase A2: h1 rows j0..j0+63, stored transposed [jj][m]
            for (int i = tid; i < TM * KH; i += NTH) {
                int m  = i & (TM - 1);
                int jj = i >> 7;
                int j  = jj + j0;
                float arg = W0F * (sx[2 * m] * sW1a[j] + sx[2 * m + 1] * sW1b[j] + sb1[j]);
                hT[jj * TM + m] = fast_sin(arg);
            }
            __syncthreads();

            // Phase B: GEMM partial over this k-half (f32x2 packed FMAs)
            #pragma unroll 4
            for (int kk = 0; kk < KH; kk++) {
                const int k = j0 + kk;
                const ulonglong2* arow = (const ulonglong2*)(hT + kk * TM + mrow);
                ulonglong2 a01 = arow[0];
                ulonglong2 a23 = arow[1];
                ull a[4] = {a01.x, a01.y, a23.x, a23.y};
                const float* wrow = sW2 + (k << 7) + txv;
                ull w[8];
                #pragma unroll
                for (int c = 0; c < 8; c++) w[c] = dup2(wrow[c << 4]);
                #pragma unroll
                for (int p = 0; p < 4; p++)
                    #pragma unroll
                    for (int c = 0; c < 8; c++)
                        acc[p][c] = fma2(a[p], w[c], acc[p][c]);
            }
            __syncthreads();
        }

        // ---- Phase C: h2 = sin(w0*(acc+b2)); partial f = h2 @ W3 ----
        float o0[8], o1[8];
        #pragma unroll
        for (int i = 0; i < 8; i++) { o0[i] = 0.f; o1[i] = 0.f; }
        #pragma unroll
        for (int c = 0; c < 8; c++) {
            int j = jcol + c;
            float bb = sb2[j], wx = sW3x[j], wy = sW3y[j];
            #pragma unroll
            for (int p = 0; p < 4; p++) {
                float lo, hi;
                unpack2(acc[p][c], lo, hi);
                float hlo = fast_sin(W0F * (lo + bb));
                float hhi = fast_sin(W0F * (hi + bb));
                o0[2 * p]     = fmaf(hlo, wx, o0[2 * p]);
                o1[2 * p]     = fmaf(hlo, wy, o1[2 * p]);
                o0[2 * p + 1] = fmaf(hhi, wx, o0[2 * p + 1]);
                o1[2 * p + 1] = fmaf(hhi, wy, o1[2 * p + 1]);
            }
        }

        // red[u][m*2+c], row stride 258 floats (bank-skewed); 4128 f <= 8192
        float* red = hT;   // safe: last hT read was before the post-GEMM sync
        #pragma unroll
        for (int i = 0; i < 8; i++) {
            int m = mrow + i;
            red[txv * 258 + m * 2 + 0] = o0[i];
            red[txv * 258 + m * 2 + 1] = o1[i];
        }
        __syncthreads();

        // ---- Phase D: reduce 16 partials per (particle, dim); emit ----
        {
            const float* r = red + tid;   // tid = m*2 + c
            float s = 0.f;
            #pragma unroll
            for (int u = 0; u < 16; u++) s += r[u * 258];
            s += b3[tid & 1];
            int gi = 2 * base + tid;
            if (mode < 3) {
                float* kdst = (mode == 0) ? g_k1 : (mode == 1) ? g_k2 : g_k3;
                kdst[gi] = s;
            } else {
                float K1 = g_k1[gi], K2 = g_k2[gi], K3 = g_k3[gi];
                float y1 = g_y[gi] + (K1 + 3.0f * (K2 + K3) + s) * (dt * 0.125f);
                g_y[gi] = y1;
                out[(size_t)(step + 1) * (NPART * 2) + gi] = y1;
            }
        }
        __syncthreads();  // before next tile reuses sx / hT
    }
}

// ---------------------------------------------------------------------------
// Host launcher: graph-capturable, allocation-free.
// Inputs (metadata order): t, x0, W1, b1, W2, b2, W3, b3. Output float32.
// ---------------------------------------------------------------------------
extern "C" void kernel_launch(void* const* d_in, const int* in_sizes, int n_in,
                              void* d_out, int out_size) {
    const float* t  = (const float*)d_in[0];
    const float* x0 = (const float*)d_in[1];
    const float* W1 = (const float*)d_in[2];
    const float* b1 = (const float*)d_in[3];
    const float* W2 = (const float*)d_in[4];
    const float* b2 = (const float*)d_in[5];
    const float* W3 = (const float*)d_in[6];
    const float* b3 = (const float*)d_in[7];
    float* out = (float*)d_out;

    const size_t state_bytes = (size_t)NPART * 2 * sizeof(float);

    cudaMemcpyAsync(out, x0, state_bytes, cudaMemcpyDeviceToDevice);
    cudaMemcpyToSymbolAsync(g_y, x0, state_bytes, 0, cudaMemcpyDeviceToDevice);

    const int smem_bytes =
        (WD * WD + KH * TM + 2 * TM + 6 * WD) * (int)sizeof(float);  // 102400 B
    cudaFuncSetAttribute(ode_eval_kernel,
                         cudaFuncAttributeMaxDynamicSharedMemorySize, smem_bytes);

    int nsm = 148;
    cudaDeviceGetAttribute(&nsm, cudaDevAttrMultiProcessorCount, 0);
    const int grid = 2 * nsm;   // 2 CTAs per SM

    for (int s = 0; s < TSTEPS - 1; s++) {
        ode_eval_kernel<<<grid, NTH, smem_bytes>>>(t, W1, b1, W2, b2, W3, b3, out,
                                                   s, 0, 0.f, 0.f, 0.f);
        ode_eval_kernel<<<grid, NTH, smem_bytes>>>(t, W1, b1, W2, b2, W3, b3, out,
                                                   s, 1, 1.0f / 3.0f, 0.f, 0.f);
        ode_eval_kernel<<<grid, NTH, smem_bytes>>>(t, W1, b1, W2, b2, W3, b3, out,
                                                   s, 2, -1.0f / 3.0f, 1.f, 0.f);
        ode_eval_kernel<<<grid, NTH, smem_bytes>>>(t, W1, b1, W2, b2, W3, b3, out,
                                                   s, 3, 1.f, -1.f, 1.f);
    }
}